// round 1
// baseline (speedup 1.0000x reference)
#include <cuda_runtime.h>

#define HID   64
#define NVOC  64
#define SD    32
#define FD    16
#define SLD   16
#define NB    256
#define SEQL  2048

// LUT scratch: per vocab id, 64 floats = [k_sem(32) | k_fast(16) | k_slow(16)]
__device__ float g_lut[NVOC * 64];
// inv(k.k + 1e-6) per id: [0..63]=sem, [64..127]=fast, [128..191]=slow
__device__ float g_inv[3 * NVOC];

// ---------------------------------------------------------------------------
// Kernel 1: build the per-token-id LUT (encoder + projections are token-id-only)
// grid = 64 blocks (one per vocab id), 128 threads
// ---------------------------------------------------------------------------
__global__ void lut_kernel(const float* __restrict__ embed,
                           const float* __restrict__ w1, const float* __restrict__ b1,
                           const float* __restrict__ w2, const float* __restrict__ b2,
                           const float* __restrict__ ln_g, const float* __restrict__ ln_b,
                           const float* __restrict__ sem_w, const float* __restrict__ sem_b,
                           const float* __restrict__ fast_w, const float* __restrict__ fast_b,
                           const float* __restrict__ slow_w, const float* __restrict__ slow_b)
{
    const int v = blockIdx.x;
    const int j = threadIdx.x;   // 0..127

    __shared__ float e[64];
    __shared__ float h1[128];
    __shared__ float x[64];
    __shared__ float xn[64];
    __shared__ float kk[64];

    if (j < 64) e[j] = embed[v * 64 + j];
    __syncthreads();

    // FFN layer 1: h1[j] = relu(sum_d e[d] * w1[d][j] + b1[j]),  w1 is [64,128] row-major
    {
        float acc = b1[j];
        #pragma unroll 8
        for (int d = 0; d < 64; d++) acc = fmaf(e[d], w1[d * 128 + j], acc);
        h1[j] = fmaxf(acc, 0.0f);
    }
    __syncthreads();

    // FFN layer 2 + residual: x[j] = e[j] + sum_d h1[d] * w2[d][j] + b2[j],  w2 is [128,64]
    if (j < 64) {
        float acc = b2[j];
        #pragma unroll 8
        for (int d = 0; d < 128; d++) acc = fmaf(h1[d], w2[d * 64 + j], acc);
        x[j] = e[j] + acc;
    }
    __syncthreads();

    // LayerNorm (redundant per-thread stats over 64 values; broadcast LDS, trivial)
    if (j < 64) {
        float mu = 0.0f;
        #pragma unroll 8
        for (int d = 0; d < 64; d++) mu += x[d];
        mu *= (1.0f / 64.0f);
        float var = 0.0f;
        #pragma unroll 8
        for (int d = 0; d < 64; d++) { float dd = x[d] - mu; var = fmaf(dd, dd, var); }
        var *= (1.0f / 64.0f);
        float r = rsqrtf(var + 1e-5f);
        xn[j] = (x[j] - mu) * r * ln_g[j] + ln_b[j];
    }
    __syncthreads();

    // Projections into the packed key vector [sem(32) | fast(16) | slow(16)]
    if (j < 64) {
        float s;
        if (j < 32) {
            s = sem_b[j];
            #pragma unroll 8
            for (int d = 0; d < 64; d++) s = fmaf(xn[d], sem_w[d * SD + j], s);
        } else if (j < 48) {
            const int c = j - 32;
            s = fast_b[c];
            #pragma unroll 8
            for (int d = 0; d < 64; d++) s = fmaf(xn[d], fast_w[d * FD + c], s);
        } else {
            const int c = j - 48;
            s = slow_b[c];
            #pragma unroll 8
            for (int d = 0; d < 64; d++) s = fmaf(xn[d], slow_w[d * SLD + c], s);
        }
        kk[j] = s;
        g_lut[v * 64 + j] = s;
    }
    __syncthreads();

    // Precompute 1/(k.k + eps) for each of the three keys
    if (j < 3) {
        const int lo = (j == 0) ? 0 : (j == 1) ? 32 : 48;
        const int hi = (j == 0) ? 32 : (j == 1) ? 48 : 64;
        float s = 0.0f;
        for (int d = lo; d < hi; d++) s = fmaf(kk[d], kk[d], s);
        g_inv[j * NVOC + v] = 1.0f / (s + 1e-6f);
    }
}

// ---------------------------------------------------------------------------
// Kernel 2: per-batch delta-rule scan over 2047 steps + fused readout
// grid = 256 blocks (one per batch), 64 threads
//   warp 0: Ms (32x32), thread i holds row i in registers
//   warp 1: lanes 0..15 hold Mef rows, lanes 16..31 hold Mes rows
// ---------------------------------------------------------------------------
__global__ void __launch_bounds__(64, 8)
scan_kernel(const int* __restrict__ seq,
            const float* __restrict__ out_w,
            const float* __restrict__ out_b,
            float* __restrict__ out)
{
    __shared__ float s_lut[NVOC * 64];
    __shared__ float s_inv[3 * NVOC];
    __shared__ int   s_seq[SEQL];
    __shared__ float s_c[64];

    const int b   = blockIdx.x;
    const int tid = threadIdx.x;

    for (int i = tid; i < NVOC * 64; i += 64) s_lut[i] = g_lut[i];
    for (int i = tid; i < 3 * NVOC;  i += 64) s_inv[i] = g_inv[i];
    {
        const int* sq = seq + b * SEQL;
        for (int i = tid; i < SEQL; i += 64) s_seq[i] = sq[i];
    }
    __syncthreads();

    const int lane = tid & 31;

    if (tid < 32) {
        // ------------------- Ms: 32x32, w = 1 -------------------
        float m[SD];
        #pragma unroll
        for (int j = 0; j < SD; j++) m[j] = 0.0f;

        for (int t = 0; t < SEQL - 1; t++) {
            const int tok = s_seq[t];
            const float4* kp = reinterpret_cast<const float4*>(&s_lut[tok * 64]);
            float k[SD];
            #pragma unroll
            for (int q = 0; q < SD / 4; q++) {
                float4 kv = kp[q];
                k[4*q+0] = kv.x; k[4*q+1] = kv.y; k[4*q+2] = kv.z; k[4*q+3] = kv.w;
            }
            const float ki  = s_lut[tok * 64 + lane];
            const float ikk = s_inv[tok];

            float a0 = 0.f, a1 = 0.f, a2 = 0.f, a3 = 0.f;
            #pragma unroll
            for (int j = 0; j < SD; j += 4) {
                a0 = fmaf(m[j+0], k[j+0], a0);
                a1 = fmaf(m[j+1], k[j+1], a1);
                a2 = fmaf(m[j+2], k[j+2], a2);
                a3 = fmaf(m[j+3], k[j+3], a3);
            }
            const float vp = (a0 + a1) + (a2 + a3);
            const float dv = fmaf(-vp, ikk, ki);   // k[i] - vp * inv_kk
            #pragma unroll
            for (int j = 0; j < SD; j++) m[j] = fmaf(dv, k[j], m[j]);
        }

        // readout key = last token
        {
            const int tok = s_seq[SEQL - 1];
            const float4* kp = reinterpret_cast<const float4*>(&s_lut[tok * 64]);
            float a0 = 0.f, a1 = 0.f, a2 = 0.f, a3 = 0.f;
            #pragma unroll
            for (int q = 0; q < SD / 4; q++) {
                float4 kv = kp[q];
                a0 = fmaf(m[4*q+0], kv.x, a0);
                a1 = fmaf(m[4*q+1], kv.y, a1);
                a2 = fmaf(m[4*q+2], kv.z, a2);
                a3 = fmaf(m[4*q+3], kv.w, a3);
            }
            s_c[lane] = (a0 + a1) + (a2 + a3);
        }
    } else {
        // ------------------- Mef / Mes: 16x16 -------------------
        const bool isf = (lane < 16);
        const int  r   = lane & 15;
        const int  off = isf ? 32 : 48;                 // position in packed key
        const float* invp = &s_inv[isf ? NVOC : 2 * NVOC];
        const float invL = 1.0f / (float)SEQL;

        float m[FD];
        #pragma unroll
        for (int j = 0; j < FD; j++) m[j] = 0.0f;

        for (int t = 0; t < SEQL - 1; t++) {
            const int tok  = s_seq[t];
            const int base = tok * 64 + off;
            const float4* kp = reinterpret_cast<const float4*>(&s_lut[base]);
            float k[FD];
            #pragma unroll
            for (int q = 0; q < FD / 4; q++) {
                float4 kv = kp[q];
                k[4*q+0] = kv.x; k[4*q+1] = kv.y; k[4*q+2] = kv.z; k[4*q+3] = kv.w;
            }
            const float kr  = s_lut[base + r];
            const float ikk = invp[tok];
            float wt = (float)(t + 1) * invL;           // w_fast
            if (!isf) wt = sqrtf(wt);                   // w_slow

            float a0 = 0.f, a1 = 0.f, a2 = 0.f, a3 = 0.f;
            #pragma unroll
            for (int j = 0; j < FD; j += 4) {
                a0 = fmaf(m[j+0], k[j+0], a0);
                a1 = fmaf(m[j+1], k[j+1], a1);
                a2 = fmaf(m[j+2], k[j+2], a2);
                a3 = fmaf(m[j+3], k[j+3], a3);
            }
            const float vp  = (a0 + a1) + (a2 + a3);
            const float dv  = fmaf(-vp, ikk, kr);
            const float wdv = wt * dv;
            #pragma unroll
            for (int j = 0; j < FD; j++) m[j] = fmaf(wdv, k[j], m[j]);
        }

        {
            const int tok  = s_seq[SEQL - 1];
            const int base = tok * 64 + off;
            const float4* kp = reinterpret_cast<const float4*>(&s_lut[base]);
            float a0 = 0.f, a1 = 0.f, a2 = 0.f, a3 = 0.f;
            #pragma unroll
            for (int q = 0; q < FD / 4; q++) {
                float4 kv = kp[q];
                a0 = fmaf(m[4*q+0], kv.x, a0);
                a1 = fmaf(m[4*q+1], kv.y, a1);
                a2 = fmaf(m[4*q+2], kv.z, a2);
                a3 = fmaf(m[4*q+3], kv.w, a3);
            }
            s_c[off + r] = (a0 + a1) + (a2 + a3);       // cef at 32.., ces at 48..
        }
    }
    __syncthreads();

    // readout: out[b][v] = sum_d c[d] * out_w[d][v] + out_b[v]   (out_w is [64,64])
    {
        float acc = out_b[tid];
        #pragma unroll 8
        for (int d = 0; d < 64; d++) acc = fmaf(s_c[d], out_w[d * 64 + tid], acc);
        out[b * 64 + tid] = acc;
    }
}

// ---------------------------------------------------------------------------
extern "C" void kernel_launch(void* const* d_in, const int* in_sizes, int n_in,
                              void* d_out, int out_size)
{
    const int*   seq    = (const int*)  d_in[0];
    const float* embed  = (const float*)d_in[1];
    const float* w1     = (const float*)d_in[2];
    const float* b1     = (const float*)d_in[3];
    const float* w2     = (const float*)d_in[4];
    const float* b2     = (const float*)d_in[5];
    const float* ln_g   = (const float*)d_in[6];
    const float* ln_b   = (const float*)d_in[7];
    const float* sem_w  = (const float*)d_in[8];
    const float* sem_b  = (const float*)d_in[9];
    const float* fast_w = (const float*)d_in[10];
    const float* fast_b = (const float*)d_in[11];
    const float* slow_w = (const float*)d_in[12];
    const float* slow_b = (const float*)d_in[13];
    const float* out_w  = (const float*)d_in[14];
    const float* out_b  = (const float*)d_in[15];
    float* out = (float*)d_out;

    lut_kernel<<<NVOC, 128>>>(embed, w1, b1, w2, b2, ln_g, ln_b,
                              sem_w, sem_b, fast_w, fast_b, slow_w, slow_b);
    scan_kernel<<<NB, 64>>>(seq, out_w, out_b, out);
}